// round 12
// baseline (speedup 1.0000x reference)
#include <cuda_runtime.h>
#include <cuda_fp16.h>
#include <math_constants.h>
#include <cstdint>

#define BB   4
#define TT   2048
#define DD   512
#define NH   8
#define NKV  4
#define HD   64
#define NTOK (BB*TT)          // 8192

// ---------------- scratch (device globals: allocation-free) ----------------
__device__ float g_q[(size_t)NTOK * DD];            // qkv out (q, fp32)
__device__ float g_k[(size_t)NTOK * NKV * HD];      // qkv out (k, fp32)
__device__ float g_v[(size_t)NTOK * NKV * HD];      // qkv out (v, fp32)

// packed pair buffers: uint2 {big, small} interleaved (GEMM operands)
__device__ uint2 g_xp[(size_t)NTOK * 256];          // x packed   [8192][256]
__device__ uint2 g_wqp[512 * 256];
__device__ uint2 g_wkp[256 * 256];
__device__ uint2 g_wvp[256 * 256];
__device__ uint2 g_wpp[512 * 256];
__device__ uint2 g_yp[(size_t)NTOK * 256];          // attn out packed

// separate big/small (attention operands)
__device__ uint32_t g_qpb[(size_t)NTOK * NH * 32],  g_qps[(size_t)NTOK * NH * 32];
__device__ uint32_t g_kpb[(size_t)NTOK * NKV * 32], g_kps[(size_t)NTOK * NKV * 32];
__device__ uint32_t g_vpb[(size_t)NTOK * NKV * 32], g_vps[(size_t)NTOK * NKV * 32];

// ------------------------------ helpers ------------------------------------
__device__ __forceinline__ void split2(float x, float y, uint32_t& b, uint32_t& s) {
    __half hbx = __float2half_rn(x);
    __half hby = __float2half_rn(y);
    float rx = x - __half2float(hbx);
    float ry = y - __half2float(hby);
    __half2 hb = __halves2half2(hbx, hby);
    __half2 hs = __halves2half2(__float2half_rn(rx), __float2half_rn(ry));
    b = *reinterpret_cast<uint32_t*>(&hb);
    s = *reinterpret_cast<uint32_t*>(&hs);
}

__device__ __forceinline__ float fexp2(float x) {
    float y;
    asm("ex2.approx.f32 %0, %1;" : "=f"(y) : "f"(x));
    return y;
}

__device__ __forceinline__ void mma_f16(float c[4], uint32_t a0, uint32_t a1,
                                        uint32_t a2, uint32_t a3,
                                        uint32_t b0, uint32_t b1) {
    asm volatile(
        "mma.sync.aligned.m16n8k16.row.col.f32.f16.f16.f32 "
        "{%0,%1,%2,%3},{%4,%5,%6,%7},{%8,%9},{%0,%1,%2,%3};"
        : "+f"(c[0]), "+f"(c[1]), "+f"(c[2]), "+f"(c[3])
        : "r"(a0), "r"(a1), "r"(a2), "r"(a3), "r"(b0), "r"(b1));
}

__device__ __forceinline__ void cp16(void* dst, const void* src) {
    uint32_t d = (uint32_t)__cvta_generic_to_shared(dst);
    asm volatile("cp.async.ca.shared.global [%0], [%1], 16;" :: "r"(d), "l"(src));
}
__device__ __forceinline__ void cp_commit() {
    asm volatile("cp.async.commit_group;");
}
template<int N> __device__ __forceinline__ void cp_wait() {
    asm volatile("cp.async.wait_group %0;" :: "n"(N));
}

// ---------------------------------------------------------------------------
// convert_all: fp32 -> packed fp16x2 {big,small} pairs for x + 4 weights.
// One float4 (2 pairs) per thread.
// ---------------------------------------------------------------------------
#define XP_PAIRS  2097152           // 8192*256
#define WQ_END    (XP_PAIRS + 131072)
#define WK_END    (WQ_END + 65536)
#define WV_END    (WK_END + 65536)
#define WP_END    (WV_END + 131072) // 2490368 total pairs

__global__ __launch_bounds__(256) void convert_all(const float* __restrict__ x,
                                                   const float* __restrict__ wq,
                                                   const float* __restrict__ wk,
                                                   const float* __restrict__ wv,
                                                   const float* __restrict__ wp) {
    size_t pb = ((size_t)blockIdx.x * 256 + threadIdx.x) * 2;
    if (pb >= WP_END) return;
    const float* src;
    uint2* dst;
    size_t off;
    if (pb < XP_PAIRS)    { src = x;  dst = g_xp;  off = pb; }
    else if (pb < WQ_END) { src = wq; dst = g_wqp; off = pb - XP_PAIRS; }
    else if (pb < WK_END) { src = wk; dst = g_wkp; off = pb - WQ_END; }
    else if (pb < WV_END) { src = wv; dst = g_wvp; off = pb - WK_END; }
    else                  { src = wp; dst = g_wpp; off = pb - WV_END; }
    float4 v = *(const float4*)(src + off * 2);
    uint32_t b0, s0, b1, s1;
    split2(v.x, v.y, b0, s0);
    split2(v.z, v.w, b1, s1);
    dst[off]     = make_uint2(b0, s0);
    dst[off + 1] = make_uint2(b1, s1);
}

// ---------------------------------------------------------------------------
// fp16x3 GEMM body: operands pre-split interleaved uint2 pairs, rows of 256.
// BM=128, BN=64, BK=32 (16 pairs), 256 threads, warp grid 4x2, tile 32x32.
// 2-stage cp.async smem pipeline. No in-loop conversion.
// ---------------------------------------------------------------------------
__device__ __forceinline__ void gemm_issue(const uint2* __restrict__ Ap,
                                           const uint2* __restrict__ Wp,
                                           uint2* As, uint2* Ws, int kp, int tid) {
#pragma unroll
    for (int i = 0; i < 4; i++) {
        int ch = tid + (i << 8);
        int r = ch >> 3, c = ch & 7;
        cp16(As + r * 20 + (c << 1), Ap + (size_t)r * 256 + kp + (c << 1));
    }
#pragma unroll
    for (int i = 0; i < 2; i++) {
        int ch = tid + (i << 8);
        int r = ch >> 3, c = ch & 7;
        cp16(Ws + r * 20 + (c << 1), Wp + (size_t)r * 256 + kp + (c << 1));
    }
    cp_commit();
}

__device__ __forceinline__ void gemm_body(const uint2* __restrict__ A,
                                          const uint2* __restrict__ W,
                                          float* __restrict__ C, int M,
                                          int rb, int cb) {
    extern __shared__ uint2 smg[];
    uint2* Ast[2] = {smg, smg + 2560};          // [128][20] each
    uint2* Wst[2] = {smg + 5120, smg + 6400};   // [64][20] each
    const int tid  = threadIdx.x;
    const int warp = tid >> 5, lane = tid & 31;
    const int gid = lane >> 2, tig = lane & 3;
    const int wm = warp >> 1, wn = warp & 1;    // 4 x 2

    const uint2* Ap = A + (size_t)rb * 256;
    const uint2* Wp = W + (size_t)cb * 256;

    float acc[2][4][4] = {};

    gemm_issue(Ap, Wp, Ast[0], Wst[0], 0, tid);
    for (int kb = 0; kb < 16; kb++) {
        if (kb < 15) {
            gemm_issue(Ap, Wp, Ast[(kb + 1) & 1], Wst[(kb + 1) & 1], (kb + 1) << 4, tid);
            cp_wait<1>();
        } else {
            cp_wait<0>();
        }
        __syncthreads();
        const uint2* Asm_ = Ast[kb & 1];
        const uint2* Wsm_ = Wst[kb & 1];
#pragma unroll
        for (int ks = 0; ks < 2; ks++) {
            int dp = (ks << 3) + tig;
            uint2 af[2][4];
#pragma unroll
            for (int mt = 0; mt < 2; mt++) {
                int row = (wm << 5) + (mt << 4) + gid;
                af[mt][0] = Asm_[row * 20 + dp];
                af[mt][1] = Asm_[(row + 8) * 20 + dp];
                af[mt][2] = Asm_[row * 20 + dp + 4];
                af[mt][3] = Asm_[(row + 8) * 20 + dp + 4];
            }
#pragma unroll
            for (int nt = 0; nt < 4; nt++) {
                int nrow = (wn << 5) + (nt << 3) + gid;
                uint2 bf0 = Wsm_[nrow * 20 + dp], bf1 = Wsm_[nrow * 20 + dp + 4];
#pragma unroll
                for (int mt = 0; mt < 2; mt++) {
                    mma_f16(acc[mt][nt], af[mt][0].x, af[mt][1].x, af[mt][2].x, af[mt][3].x, bf0.x, bf1.x);
                    mma_f16(acc[mt][nt], af[mt][0].x, af[mt][1].x, af[mt][2].x, af[mt][3].x, bf0.y, bf1.y);
                    mma_f16(acc[mt][nt], af[mt][0].y, af[mt][1].y, af[mt][2].y, af[mt][3].y, bf0.x, bf1.x);
                }
            }
        }
        __syncthreads();
    }
#pragma unroll
    for (int mt = 0; mt < 2; mt++)
#pragma unroll
        for (int nt = 0; nt < 4; nt++) {
            int row = rb + (wm << 5) + (mt << 4) + gid;
            int col = cb + (wn << 5) + (nt << 3) + (tig << 1);
            *(float2*)(C + (size_t)row * M + col)       = make_float2(acc[mt][nt][0], acc[mt][nt][1]);
            *(float2*)(C + (size_t)(row + 8) * M + col) = make_float2(acc[mt][nt][2], acc[mt][nt][3]);
        }
}

// Fused QKV projections from packed operands.
__global__ __launch_bounds__(256) void qkv_gemm() {
    const int bx = blockIdx.x;
    const uint2* W;
    float* C;
    int M, cb;
    if (bx < 8)       { W = g_wqp; C = g_q; M = 512; cb = bx << 6; }
    else if (bx < 12) { W = g_wkp; C = g_k; M = 256; cb = (bx - 8) << 6; }
    else              { W = g_wvp; C = g_v; M = 256; cb = (bx - 12) << 6; }
    gemm_body(g_xp, W, C, M, blockIdx.y << 7, cb);
}

// Output projection: reads packed attention output + packed w_proj.
__global__ __launch_bounds__(256) void outproj_gemm(float* __restrict__ out) {
    gemm_body(g_yp, g_wpp, out, 512, blockIdx.y << 7, blockIdx.x << 6);
}

// ---------------------------------------------------------------------------
// normrope_pack: RMSNorm + RoPE + gain/scale, writes packed big/small pairs.
// One warp per (token, head); lane l handles dim pair (2l, 2l+1).
// q: layout [(b*8+h)*2048 + t][32];  k: [(b*4+kvh)*2048 + t][32]
// ---------------------------------------------------------------------------
__global__ __launch_bounds__(256) void normrope_pack(const float* __restrict__ qg) {
    const int w    = (blockIdx.x * blockDim.x + threadIdx.x) >> 5;
    const int lane = threadIdx.x & 31;
    const int NQ = NTOK * NH;
    const float* srcp;
    uint32_t *dstb, *dsts;
    size_t didx;
    int pos;
    float mult;
    if (w < NQ) {
        int tok = w >> 3, h = w & 7;
        srcp = g_q + (size_t)tok * DD + h * HD;
        pos  = tok & (TT - 1);
        mult = qg[h] * 0.125f * 1.44269504088896340736f;   // gain/sqrt(64)*log2e
        didx = ((size_t)((tok >> 11) * NH + h) * TT + pos) * 32 + lane;
        dstb = g_qpb; dsts = g_qps;
    } else {
        int w2 = w - NQ;
        if (w2 >= NTOK * NKV) return;
        int tok = w2 >> 2, kvh = w2 & 3;
        srcp = g_k + (size_t)tok * (NKV * HD) + kvh * HD;
        pos  = tok & (TT - 1);
        mult = 1.0f;
        didx = ((size_t)((tok >> 11) * NKV + kvh) * TT + pos) * 32 + lane;
        dstb = g_kpb; dsts = g_kps;
    }
    float2 v = ((const float2*)srcp)[lane];
    float ss = v.x * v.x + v.y * v.y;
#pragma unroll
    for (int o = 16; o > 0; o >>= 1) ss += __shfl_xor_sync(0xffffffffu, ss, o);
    const float rn = rsqrtf(ss * (1.0f / 64.0f) + 1.1920929e-7f);
    v.x *= rn; v.y *= rn;

    // RoPE: lanes 0..3 hold x1 dims (0..7), lanes 4..7 hold x2 dims (8..15).
    float ox = __shfl_xor_sync(0xffffffffu, v.x, 4);
    float oy = __shfl_xor_sync(0xffffffffu, v.y, 4);
    if (lane < 8) {
        int j0 = (lane & 3) << 1;                       // freq idx for .x
        float a0 = (float)pos * powf(10000.0f, -(float)j0 * 0.125f);
        float a1 = (float)pos * powf(10000.0f, -(float)(j0 + 1) * 0.125f);
        float s0_, c0_, s1_, c1_;
        sincosf(a0, &s0_, &c0_);
        sincosf(a1, &s1_, &c1_);
        if (lane < 4) { v.x = v.x * c0_ + ox * s0_;  v.y = v.y * c1_ + oy * s1_; }
        else          { v.x = v.x * c0_ - ox * s0_;  v.y = v.y * c1_ - oy * s1_; }
    }
    v.x *= mult; v.y *= mult;
    uint32_t b, s;
    split2(v.x, v.y, b, s);
    dstb[didx] = b;
    dsts[didx] = s;
}

// ---------------------------------------------------------------------------
// convert_v: fp32 v -> key-paired packed layout [(b*4+kvh)*1024 + kp][64],
// half2 = (v[2kp][d], v[2kp+1][d]).
// ---------------------------------------------------------------------------
__global__ __launch_bounds__(256) void convert_v() {
    int f = blockIdx.x * 256 + threadIdx.x;        // < 4*4*1024*64 = 1048576
    int d   = f & 63;
    int kp  = (f >> 6) & 1023;
    int kvh = (f >> 16) & 3;
    int b   = f >> 18;
    size_t tok0 = (size_t)b * TT + (kp << 1);
    float v0 = g_v[(tok0 * NKV + kvh) * HD + d];
    float v1 = g_v[((tok0 + 1) * NKV + kvh) * HD + d];
    uint32_t bb, ss;
    split2(v0, v1, bb, ss);
    size_t o = ((size_t)(b * NKV + kvh) * (TT / 2) + kp) * 64 + d;
    g_vpb[o] = bb;
    g_vps[o] = ss;
}

// ---------------------------------------------------------------------------
// Flash attention, fp16x3, exp2-domain softmax. MMA/softmax identical to the
// proven R7 kernel; tile loads are cp.async of pre-split contiguous tiles.
// Epilogue writes packed uint2 pairs for the out-projection.
// ---------------------------------------------------------------------------
__global__ __launch_bounds__(128) void attn_f16() {
    __shared__ __align__(16) uint32_t Kpb[64][36], Kps[64][36];   // [key][dp]
    __shared__ __align__(16) uint32_t Vpb[32][72], Vps[32][72];   // [kp][d]

    const int tid  = threadIdx.x;
    const int warp = tid >> 5, lane = tid & 31;
    const int gid = lane >> 2, tig = lane & 3;
    const int rowbase = warp << 4;

    const int qt  = gridDim.x - 1 - blockIdx.x;    // heavy tiles first
    const int bh  = blockIdx.y;
    const int b   = bh >> 3, h = bh & 7, kvh = h >> 1;
    const float NEG = -CUDART_INF_F;

    // Q fragments direct from packed gmem (no conversion)
    uint32_t qb[4][4], qs[4][4];
    {
        const uint32_t* qbp = g_qpb + ((size_t)(b * NH + h) * TT + qt * 64 + rowbase) * 32;
        const uint32_t* qsp = g_qps + ((size_t)(b * NH + h) * TT + qt * 64 + rowbase) * 32;
#pragma unroll
        for (int ks = 0; ks < 4; ks++) {
            int dp = (ks << 3) + tig;
            qb[ks][0] = qbp[gid * 32 + dp];
            qb[ks][1] = qbp[(gid + 8) * 32 + dp];
            qb[ks][2] = qbp[gid * 32 + dp + 4];
            qb[ks][3] = qbp[(gid + 8) * 32 + dp + 4];
            qs[ks][0] = qsp[gid * 32 + dp];
            qs[ks][1] = qsp[(gid + 8) * 32 + dp];
            qs[ks][2] = qsp[gid * 32 + dp + 4];
            qs[ks][3] = qsp[(gid + 8) * 32 + dp + 4];
        }
    }

    float oacc[8][4] = {};
    float m0 = NEG, m1 = NEG, l0 = 0.0f, l1 = 0.0f;

    const uint32_t* kb_src = g_kpb + ((size_t)(b * NKV + kvh) * TT) * 32;
    const uint32_t* ks_src = g_kps + ((size_t)(b * NKV + kvh) * TT) * 32;
    const uint32_t* vb_src = g_vpb + ((size_t)(b * NKV + kvh) * (TT / 2)) * 64;
    const uint32_t* vs_src = g_vps + ((size_t)(b * NKV + kvh) * (TT / 2)) * 64;

    for (int kt = 0; kt <= qt; kt++) {
        __syncthreads();                           // all warps done with tiles
        {
            const uint32_t* kbt = kb_src + (size_t)kt * 2048;   // 64x32 contiguous
            const uint32_t* kst = ks_src + (size_t)kt * 2048;
            const uint32_t* vbt = vb_src + (size_t)kt * 2048;   // 32x64 contiguous
            const uint32_t* vst = vs_src + (size_t)kt * 2048;
#pragma unroll
            for (int i = 0; i < 4; i++) {
                int ch = tid + (i << 7);
                int r = ch >> 3, c = ch & 7;
                cp16(&Kpb[r][c << 2], kbt + r * 32 + (c << 2));
                cp16(&Kps[r][c << 2], kst + r * 32 + (c << 2));
            }
#pragma unroll
            for (int i = 0; i < 4; i++) {
                int ch = tid + (i << 7);
                int r = ch >> 4, c = ch & 15;
                cp16(&Vpb[r][c << 2], vbt + (r << 6) + (c << 2));
                cp16(&Vps[r][c << 2], vst + (r << 6) + (c << 2));
            }
            cp_commit();
            cp_wait<0>();
        }
        __syncthreads();

        // S = Q K^T  (fp16x3) -- S already in log2 domain
        float sacc[8][4] = {};
#pragma unroll
        for (int ks = 0; ks < 4; ks++) {
            int dp = (ks << 3) + tig;
#pragma unroll
            for (int nt = 0; nt < 8; nt++) {
                int key = (nt << 3) + gid;
                uint32_t kb0 = Kpb[key][dp], kb1 = Kpb[key][dp + 4];
                uint32_t ks0 = Kps[key][dp], ks1 = Kps[key][dp + 4];
                mma_f16(sacc[nt], qb[ks][0], qb[ks][1], qb[ks][2], qb[ks][3], kb0, kb1);
                mma_f16(sacc[nt], qb[ks][0], qb[ks][1], qb[ks][2], qb[ks][3], ks0, ks1);
                mma_f16(sacc[nt], qs[ks][0], qs[ks][1], qs[ks][2], qs[ks][3], kb0, kb1);
            }
        }

        if (kt == qt) {                            // causal mask on diagonal tile
            int r0 = rowbase + gid, r1 = r0 + 8;
#pragma unroll
            for (int nt = 0; nt < 8; nt++) {
                int c0 = (nt << 3) + (tig << 1), c1 = c0 + 1;
                if (c0 > r0) sacc[nt][0] = NEG;
                if (c1 > r0) sacc[nt][1] = NEG;
                if (c0 > r1) sacc[nt][2] = NEG;
                if (c1 > r1) sacc[nt][3] = NEG;
            }
        }

        // online softmax in exp2 domain
        float mt0 = NEG, mt1 = NEG;
#pragma unroll
        for (int nt = 0; nt < 8; nt++) {
            mt0 = fmaxf(mt0, fmaxf(sacc[nt][0], sacc[nt][1]));
            mt1 = fmaxf(mt1, fmaxf(sacc[nt][2], sacc[nt][3]));
        }
        mt0 = fmaxf(mt0, __shfl_xor_sync(0xffffffffu, mt0, 1));
        mt0 = fmaxf(mt0, __shfl_xor_sync(0xffffffffu, mt0, 2));
        mt1 = fmaxf(mt1, __shfl_xor_sync(0xffffffffu, mt1, 1));
        mt1 = fmaxf(mt1, __shfl_xor_sync(0xffffffffu, mt1, 2));

        float mn0 = fmaxf(m0, mt0), mn1 = fmaxf(m1, mt1);
        float al0 = fexp2(m0 - mn0), al1 = fexp2(m1 - mn1);
        m0 = mn0; m1 = mn1;

        float rs0 = 0.0f, rs1 = 0.0f;
#pragma unroll
        for (int nt = 0; nt < 8; nt++) {
            sacc[nt][0] = fexp2(sacc[nt][0] - m0);
            sacc[nt][1] = fexp2(sacc[nt][1] - m0);
            sacc[nt][2] = fexp2(sacc[nt][2] - m1);
            sacc[nt][3] = fexp2(sacc[nt][3] - m1);
            rs0 += sacc[nt][0] + sacc[nt][1];
            rs1 += sacc[nt][2] + sacc[nt][3];
        }
        rs0 += __shfl_xor_sync(0xffffffffu, rs0, 1);
        rs0 += __shfl_xor_sync(0xffffffffu, rs0, 2);
        rs1 += __shfl_xor_sync(0xffffffffu, rs1, 1);
        rs1 += __shfl_xor_sync(0xffffffffu, rs1, 2);
        l0 = l0 * al0 + rs0;
        l1 = l1 * al1 + rs1;
#pragma unroll
        for (int nt = 0; nt < 8; nt++) {
            oacc[nt][0] *= al0; oacc[nt][1] *= al0;
            oacc[nt][2] *= al1; oacc[nt][3] *= al1;
        }

        // O += P V  (fp16x3, P fragments from registers)
#pragma unroll
        for (int ks = 0; ks < 4; ks++) {
            uint32_t pb[4], ps[4];
            split2(sacc[2*ks][0],     sacc[2*ks][1],     pb[0], ps[0]);
            split2(sacc[2*ks][2],     sacc[2*ks][3],     pb[1], ps[1]);
            split2(sacc[2*ks + 1][0], sacc[2*ks + 1][1], pb[2], ps[2]);
            split2(sacc[2*ks + 1][2], sacc[2*ks + 1][3], pb[3], ps[3]);
            int kp = (ks << 3) + tig;
#pragma unroll
            for (int nt = 0; nt < 8; nt++) {
                int d = (nt << 3) + gid;
                uint32_t vb0 = Vpb[kp][d], vb1 = Vpb[kp + 4][d];
                uint32_t vs0 = Vps[kp][d], vs1 = Vps[kp + 4][d];
                mma_f16(oacc[nt], pb[0], pb[1], pb[2], pb[3], vb0, vb1);
                mma_f16(oacc[nt], pb[0], pb[1], pb[2], pb[3], vs0, vs1);
                mma_f16(oacc[nt], ps[0], ps[1], ps[2], ps[3], vb0, vb1);
            }
        }
    }

    // epilogue: write packed pairs for out-projection
    float inv0 = 1.0f / l0, inv1 = 1.0f / l1;
    uint2* yp = g_yp + ((size_t)(b * TT + qt * 64)) * 256 + h * 32;
    int r0 = rowbase + gid, r1 = r0 + 8;
#pragma unroll
    for (int nt = 0; nt < 8; nt++) {
        int pr = (nt << 2) + tig;
        uint32_t bb, ss;
        split2(oacc[nt][0] * inv0, oacc[nt][1] * inv0, bb, ss);
        yp[(size_t)r0 * 256 + pr] = make_uint2(bb, ss);
        split2(oacc[nt][2] * inv1, oacc[nt][3] * inv1, bb, ss);
        yp[(size_t)r1 * 256 + pr] = make_uint2(bb, ss);
    }
}

// ---------------------------------------------------------------------------
extern "C" void kernel_launch(void* const* d_in, const int* in_sizes, int n_in,
                              void* d_out, int out_size) {
    (void)in_sizes; (void)n_in; (void)out_size;
    const float* x      = (const float*)d_in[0];
    const float* w_q    = (const float*)d_in[1];
    const float* w_k    = (const float*)d_in[2];
    const float* w_v    = (const float*)d_in[3];
    const float* w_proj = (const float*)d_in[4];
    const float* q_gain = (const float*)d_in[5];
    float* out = (float*)d_out;

    const int GEMM_SMEM = 7680 * sizeof(uint2);   // 61440 B
    cudaFuncSetAttribute(qkv_gemm, cudaFuncAttributeMaxDynamicSharedMemorySize, GEMM_SMEM);
    cudaFuncSetAttribute(outproj_gemm, cudaFuncAttributeMaxDynamicSharedMemorySize, GEMM_SMEM);

    convert_all<<<4864, 256>>>(x, w_q, w_k, w_v, w_proj);

    qkv_gemm<<<dim3(16, 64), 256, GEMM_SMEM>>>();

    normrope_pack<<<(NTOK * (NH + NKV)) / 8, 256>>>(q_gain);
    convert_v<<<4096, 256>>>();

    attn_f16<<<dim3(TT / 64, BB * NH), 128>>>();

    outproj_gemm<<<dim3(8, 64), 256, GEMM_SMEM>>>(out);
}

// round 13
// speedup vs baseline: 1.1626x; 1.1626x over previous
#include <cuda_runtime.h>
#include <cuda_fp16.h>
#include <math_constants.h>
#include <cstdint>

#define BB   4
#define TT   2048
#define DD   512
#define NH   8
#define NKV  4
#define HD   64
#define NTOK (BB*TT)          // 8192

// ---------------- scratch (device globals: allocation-free) ----------------
__device__ float g_q[(size_t)NTOK * DD];
__device__ float g_k[(size_t)NTOK * NKV * HD];
__device__ float g_v[(size_t)NTOK * NKV * HD];
__device__ float g_y[(size_t)NTOK * DD];

// ------------------------------ helpers ------------------------------------
// split (x,y) into fp16 big/small packed half2 pairs (fp16x3 decomposition)
__device__ __forceinline__ void split2(float x, float y, uint32_t& b, uint32_t& s) {
    __half hbx = __float2half_rn(x);
    __half hby = __float2half_rn(y);
    float rx = x - __half2float(hbx);
    float ry = y - __half2float(hby);
    __half2 hb = __halves2half2(hbx, hby);
    __half2 hs = __halves2half2(__float2half_rn(rx), __float2half_rn(ry));
    b = *reinterpret_cast<uint32_t*>(&hb);
    s = *reinterpret_cast<uint32_t*>(&hs);
}

// plain pack (no residual) for fp16x2 paths
__device__ __forceinline__ uint32_t pack2(float x, float y) {
    __half2 h = __floats2half2_rn(x, y);
    return *reinterpret_cast<uint32_t*>(&h);
}

__device__ __forceinline__ float fexp2(float x) {
    float y;
    asm("ex2.approx.f32 %0, %1;" : "=f"(y) : "f"(x));
    return y;
}

__device__ __forceinline__ void mma_f16(float c[4], uint32_t a0, uint32_t a1,
                                        uint32_t a2, uint32_t a3,
                                        uint32_t b0, uint32_t b1) {
    asm volatile(
        "mma.sync.aligned.m16n8k16.row.col.f32.f16.f16.f32 "
        "{%0,%1,%2,%3},{%4,%5,%6,%7},{%8,%9},{%0,%1,%2,%3};"
        : "+f"(c[0]), "+f"(c[1]), "+f"(c[2]), "+f"(c[3])
        : "r"(a0), "r"(a1), "r"(a2), "r"(a3), "r"(b0), "r"(b1));
}

// ---------------------------------------------------------------------------
// fp16x3 / fp16x2 GEMM body (NT): C[n,m] = sum_d A[n,d]*W[m,d].
// BM=128, BN=64, BK=32, 256 threads (8 warps), warp grid 4x2, warp tile 32x32.
// Interleaved {big,small} smem; register prefetch over the 16 k-blocks.
// FULL=true: 3-term (Ab*Wb + Ab*Ws + As*Wb). FULL=false: drop As*Wb
// (~2^-13-level extra error; used only for the final out-projection).
// ---------------------------------------------------------------------------
template<bool FULL>
__device__ __forceinline__ void gemm_body(const float* __restrict__ A,
                                          const float* __restrict__ W,
                                          float* __restrict__ C, int M,
                                          int rb, int cb) {
    __shared__ __align__(16) uint2 Asm[128][20];   // [row][kpair] {big,small}
    __shared__ __align__(16) uint2 Wsm[64][20];
    const int tid  = threadIdx.x;
    const int warp = tid >> 5, lane = tid & 31;
    const int gid = lane >> 2, tig = lane & 3;
    const int wm = warp >> 1, wn = warp & 1;       // 4 x 2

    const float* Ap = A + (size_t)rb * DD;
    const float* Wp = W + (size_t)cb * DD;

    float4 pa[4], pw[2];
#pragma unroll
    for (int i = 0; i < 4; i++) {
        int idx = tid + (i << 8);
        pa[i] = *(const float4*)(Ap + (size_t)(idx >> 3) * DD + ((idx & 7) << 2));
    }
#pragma unroll
    for (int i = 0; i < 2; i++) {
        int idx = tid + (i << 8);
        pw[i] = *(const float4*)(Wp + (size_t)(idx >> 3) * DD + ((idx & 7) << 2));
    }

    float acc[2][4][4] = {};

    for (int k0 = 0; k0 < DD; k0 += 32) {
#pragma unroll
        for (int i = 0; i < 4; i++) {
            int idx = tid + (i << 8);
            int rr = idx >> 3, cc = idx & 7;
            uint32_t b0, s0, b1, s1;
            split2(pa[i].x, pa[i].y, b0, s0); split2(pa[i].z, pa[i].w, b1, s1);
            *(uint4*)&Asm[rr][cc << 1] = make_uint4(b0, s0, b1, s1);
        }
#pragma unroll
        for (int i = 0; i < 2; i++) {
            int idx = tid + (i << 8);
            int rr = idx >> 3, cc = idx & 7;
            uint32_t b0, s0, b1, s1;
            split2(pw[i].x, pw[i].y, b0, s0); split2(pw[i].z, pw[i].w, b1, s1);
            *(uint4*)&Wsm[rr][cc << 1] = make_uint4(b0, s0, b1, s1);
        }
        __syncthreads();

        if (k0 + 32 < DD) {
#pragma unroll
            for (int i = 0; i < 4; i++) {
                int idx = tid + (i << 8);
                pa[i] = *(const float4*)(Ap + (size_t)(idx >> 3) * DD + k0 + 32 + ((idx & 7) << 2));
            }
#pragma unroll
            for (int i = 0; i < 2; i++) {
                int idx = tid + (i << 8);
                pw[i] = *(const float4*)(Wp + (size_t)(idx >> 3) * DD + k0 + 32 + ((idx & 7) << 2));
            }
        }

#pragma unroll
        for (int ks = 0; ks < 2; ks++) {
            int dp = (ks << 3) + tig;
            uint2 af[2][4];
#pragma unroll
            for (int mt = 0; mt < 2; mt++) {
                int row = (wm << 5) + (mt << 4) + gid;
                af[mt][0] = Asm[row][dp];
                af[mt][1] = Asm[row + 8][dp];
                af[mt][2] = Asm[row][dp + 4];
                af[mt][3] = Asm[row + 8][dp + 4];
            }
#pragma unroll
            for (int nt = 0; nt < 4; nt++) {
                int nrow = (wn << 5) + (nt << 3) + gid;
                uint2 bf0 = Wsm[nrow][dp], bf1 = Wsm[nrow][dp + 4];
#pragma unroll
                for (int mt = 0; mt < 2; mt++) {
                    mma_f16(acc[mt][nt], af[mt][0].x, af[mt][1].x, af[mt][2].x, af[mt][3].x, bf0.x, bf1.x);
                    mma_f16(acc[mt][nt], af[mt][0].x, af[mt][1].x, af[mt][2].x, af[mt][3].x, bf0.y, bf1.y);
                    if (FULL)
                        mma_f16(acc[mt][nt], af[mt][0].y, af[mt][1].y, af[mt][2].y, af[mt][3].y, bf0.x, bf1.x);
                }
            }
        }
        __syncthreads();
    }
#pragma unroll
    for (int mt = 0; mt < 2; mt++)
#pragma unroll
        for (int nt = 0; nt < 4; nt++) {
            int row = rb + (wm << 5) + (mt << 4) + gid;
            int col = cb + (wn << 5) + (nt << 3) + (tig << 1);
            *(float2*)(C + (size_t)row * M + col)       = make_float2(acc[mt][nt][0], acc[mt][nt][1]);
            *(float2*)(C + (size_t)(row + 8) * M + col) = make_float2(acc[mt][nt][2], acc[mt][nt][3]);
        }
}

// Fused QKV projections: blockIdx.x selects target matrix + column tile.
__global__ __launch_bounds__(256) void qkv_gemm(const float* __restrict__ x,
                                                const float* __restrict__ w_q,
                                                const float* __restrict__ w_k,
                                                const float* __restrict__ w_v,
                                                float* __restrict__ gq,
                                                float* __restrict__ gk,
                                                float* __restrict__ gv) {
    const int bx = blockIdx.x;
    const float* W;
    float* C;
    int M, cb;
    if (bx < 8)       { W = w_q; C = gq; M = 512; cb = bx << 6; }
    else if (bx < 12) { W = w_k; C = gk; M = 256; cb = (bx - 8) << 6; }
    else              { W = w_v; C = gv; M = 256; cb = (bx - 12) << 6; }
    gemm_body<true>(x, W, C, M, blockIdx.y << 7, cb);
}

// Out-projection: fp16x2 (output-linear path, error ~1e-4 — safe).
__global__ __launch_bounds__(256) void sgemm_f16(const float* __restrict__ A,
                                                 const float* __restrict__ W,
                                                 float* __restrict__ C, int M) {
    gemm_body<false>(A, W, C, M, blockIdx.y << 7, blockIdx.x << 6);
}

// ---------------------------------------------------------------------------
// Fused RMSNorm + RoPE + gain (q) / RMSNorm + RoPE (k), in place.
// Folds softmax scale 1/8 AND log2(e) into q (softmax runs in exp2 domain).
// ---------------------------------------------------------------------------
__global__ __launch_bounds__(256) void normrope_kernel(const float* __restrict__ qg) {
    const int w    = (blockIdx.x * blockDim.x + threadIdx.x) >> 5;
    const int lane = threadIdx.x & 31;
    const int NQ = NTOK * NH;
    float* p;
    int pos;
    float mult;
    if (w < NQ) {
        int tok = w >> 3, hh = w & 7;
        p    = g_q + (size_t)tok * DD + hh * HD;
        pos  = tok & (TT - 1);
        mult = qg[hh] * 0.125f * 1.44269504088896340736f;   // gain/sqrt(64)*log2e
    } else {
        int w2 = w - NQ;
        if (w2 >= NTOK * NKV) return;
        int tok = w2 >> 2, kv = w2 & 3;
        p    = g_k + (size_t)tok * (NKV * HD) + kv * HD;
        pos  = tok & (TT - 1);
        mult = 1.0f;
    }
    float v0 = p[lane];
    float v1 = p[lane + 32];
    float ss = v0 * v0 + v1 * v1;
#pragma unroll
    for (int o = 16; o > 0; o >>= 1) ss += __shfl_xor_sync(0xffffffffu, ss, o);
    const float rn = rsqrtf(ss * (1.0f / 64.0f) + 1.1920929e-7f);
    v0 *= rn; v1 *= rn;

    float other = __shfl_xor_sync(0xffffffffu, v0, 8);
    float r0 = v0;
    if (lane < 16) {
        int   fi   = lane & 7;
        float invf = powf(10000.0f, -(float)fi * 0.125f);
        float ang  = (float)pos * invf;
        float sn, cs;
        sincosf(ang, &sn, &cs);
        r0 = (lane < 8) ? (v0 * cs + other * sn) : (v0 * cs - other * sn);
    }
    p[lane]      = r0 * mult;
    p[lane + 32] = v1 * mult;
}

// ---------------------------------------------------------------------------
// Flash attention, fp16x3 scores / fp16x2 PV, exp2-domain softmax.
// Base = proven R7/R11 kernel; PV now drops the P-residual term:
// O += Pb*Vb + Pb*Vs  (P simply rounded to fp16; V keeps big+small).
// ---------------------------------------------------------------------------
__global__ __launch_bounds__(128) void attn_f16() {
    __shared__ __align__(16) uint32_t Kpb[64][36], Kps[64][36];   // [key][dp]
    __shared__ __align__(16) uint32_t Vpb[32][72], Vps[32][72];   // [kp][d]

    const int tid  = threadIdx.x;
    const int warp = tid >> 5, lane = tid & 31;
    const int gid = lane >> 2, tig = lane & 3;
    const int rowbase = warp << 4;

    const int qt  = gridDim.x - 1 - blockIdx.x;    // heavy tiles first
    const int bh  = blockIdx.y;
    const int b   = bh >> 3, h = bh & 7, kvh = h >> 1;
    const float NEG = -CUDART_INF_F;

    // Q fragments (16 rows x 64 d per warp), big/small packed half2
    uint32_t qb[4][4], qs[4][4];
    const float* qptr = g_q + (size_t)(b * TT + qt * 64 + rowbase) * DD + h * HD;
#pragma unroll
    for (int ks = 0; ks < 4; ks++) {
        int c0 = (ks << 4) + (tig << 1);
        const float* r0p = qptr + (size_t)gid * DD;
        const float* r1p = qptr + (size_t)(gid + 8) * DD;
        split2(r0p[c0],     r0p[c0 + 1], qb[ks][0], qs[ks][0]);
        split2(r1p[c0],     r1p[c0 + 1], qb[ks][1], qs[ks][1]);
        split2(r0p[c0 + 8], r0p[c0 + 9], qb[ks][2], qs[ks][2]);
        split2(r1p[c0 + 8], r1p[c0 + 9], qb[ks][3], qs[ks][3]);
    }

    float oacc[8][4] = {};
    float m0 = NEG, m1 = NEG, l0 = 0.0f, l1 = 0.0f;

    const float* kbase = g_k + ((size_t)(b * TT) * NKV + kvh) * HD;
    const float* vbase = g_v + ((size_t)(b * TT) * NKV + kvh) * HD;

    for (int kt = 0; kt <= qt; kt++) {
        __syncthreads();                           // all warps done with tiles
        const float* kp_ = kbase + (size_t)kt * 64 * (NKV * HD);
        const float* vp_ = vbase + (size_t)kt * 64 * (NKV * HD);
        // K tile: [key][dpair]
#pragma unroll
        for (int i = 0; i < 8; i++) {
            int idx = tid + (i << 7);
            int r = idx >> 4, c4 = idx & 15;
            float4 kv = *(const float4*)(kp_ + (size_t)r * (NKV * HD) + (c4 << 2));
            uint32_t b0, s0, b1, s1;
            split2(kv.x, kv.y, b0, s0); split2(kv.z, kv.w, b1, s1);
            *(uint2*)&Kpb[r][c4 << 1] = make_uint2(b0, b1);
            *(uint2*)&Kps[r][c4 << 1] = make_uint2(s0, s1);
        }
        // V tile: key-paired [kp][d], float4-based pairing
        {
            int d   = (tid & 15) << 2;
            int kp8 = tid >> 4;                    // 0..7
#pragma unroll
            for (int it = 0; it < 4; it++) {
                int kp = (it << 3) + kp8;
                const float* r0 = vp_ + (size_t)(kp << 1) * (NKV * HD) + d;
                float4 v0 = *(const float4*)r0;
                float4 v1 = *(const float4*)(r0 + NKV * HD);
                uint32_t b0, s0, b1, s1, b2, s2, b3, s3;
                split2(v0.x, v1.x, b0, s0);
                split2(v0.y, v1.y, b1, s1);
                split2(v0.z, v1.z, b2, s2);
                split2(v0.w, v1.w, b3, s3);
                *(uint4*)&Vpb[kp][d] = make_uint4(b0, b1, b2, b3);
                *(uint4*)&Vps[kp][d] = make_uint4(s0, s1, s2, s3);
            }
        }
        __syncthreads();

        // S = Q K^T  (fp16x3) -- S already in log2 domain (log2e folded into q)
        float sacc[8][4] = {};
#pragma unroll
        for (int ks = 0; ks < 4; ks++) {
            int dp = (ks << 3) + tig;
#pragma unroll
            for (int nt = 0; nt < 8; nt++) {
                int key = (nt << 3) + gid;
                uint32_t kb0 = Kpb[key][dp], kb1 = Kpb[key][dp + 4];
                uint32_t ks0 = Kps[key][dp], ks1 = Kps[key][dp + 4];
                mma_f16(sacc[nt], qb[ks][0], qb[ks][1], qb[ks][2], qb[ks][3], kb0, kb1);
                mma_f16(sacc[nt], qb[ks][0], qb[ks][1], qb[ks][2], qb[ks][3], ks0, ks1);
                mma_f16(sacc[nt], qs[ks][0], qs[ks][1], qs[ks][2], qs[ks][3], kb0, kb1);
            }
        }

        if (kt == qt) {                            // causal mask on diagonal tile
            int r0 = rowbase + gid, r1 = r0 + 8;
#pragma unroll
            for (int nt = 0; nt < 8; nt++) {
                int c0 = (nt << 3) + (tig << 1), c1 = c0 + 1;
                if (c0 > r0) sacc[nt][0] = NEG;
                if (c1 > r0) sacc[nt][1] = NEG;
                if (c0 > r1) sacc[nt][2] = NEG;
                if (c1 > r1) sacc[nt][3] = NEG;
            }
        }

        // online softmax in exp2 domain (rows rowbase+gid, rowbase+gid+8)
        float mt0 = NEG, mt1 = NEG;
#pragma unroll
        for (int nt = 0; nt < 8; nt++) {
            mt0 = fmaxf(mt0, fmaxf(sacc[nt][0], sacc[nt][1]));
            mt1 = fmaxf(mt1, fmaxf(sacc[nt][2], sacc[nt][3]));
        }
        mt0 = fmaxf(mt0, __shfl_xor_sync(0xffffffffu, mt0, 1));
        mt0 = fmaxf(mt0, __shfl_xor_sync(0xffffffffu, mt0, 2));
        mt1 = fmaxf(mt1, __shfl_xor_sync(0xffffffffu, mt1, 1));
        mt1 = fmaxf(mt1, __shfl_xor_sync(0xffffffffu, mt1, 2));

        float mn0 = fmaxf(m0, mt0), mn1 = fmaxf(m1, mt1);
        float al0 = fexp2(m0 - mn0), al1 = fexp2(m1 - mn1);
        m0 = mn0; m1 = mn1;

        float rs0 = 0.0f, rs1 = 0.0f;
#pragma unroll
        for (int nt = 0; nt < 8; nt++) {
            sacc[nt][0] = fexp2(sacc[nt][0] - m0);
            sacc[nt][1] = fexp2(sacc[nt][1] - m0);
            sacc[nt][2] = fexp2(sacc[nt][2] - m1);
            sacc[nt][3] = fexp2(sacc[nt][3] - m1);
            rs0 += sacc[nt][0] + sacc[nt][1];
            rs1 += sacc[nt][2] + sacc[nt][3];
        }
        rs0 += __shfl_xor_sync(0xffffffffu, rs0, 1);
        rs0 += __shfl_xor_sync(0xffffffffu, rs0, 2);
        rs1 += __shfl_xor_sync(0xffffffffu, rs1, 1);
        rs1 += __shfl_xor_sync(0xffffffffu, rs1, 2);
        l0 = l0 * al0 + rs0;
        l1 = l1 * al1 + rs1;
#pragma unroll
        for (int nt = 0; nt < 8; nt++) {
            oacc[nt][0] *= al0; oacc[nt][1] *= al0;
            oacc[nt][2] *= al1; oacc[nt][3] *= al1;
        }

        // O += P V  (fp16x2: P plain-rounded, V big+small)
#pragma unroll
        for (int ks = 0; ks < 4; ks++) {
            uint32_t pb[4];
            pb[0] = pack2(sacc[2*ks][0],     sacc[2*ks][1]);
            pb[1] = pack2(sacc[2*ks][2],     sacc[2*ks][3]);
            pb[2] = pack2(sacc[2*ks + 1][0], sacc[2*ks + 1][1]);
            pb[3] = pack2(sacc[2*ks + 1][2], sacc[2*ks + 1][3]);
            int kp = (ks << 3) + tig;
#pragma unroll
            for (int nt = 0; nt < 8; nt++) {
                int d = (nt << 3) + gid;
                uint32_t vb0 = Vpb[kp][d], vb1 = Vpb[kp + 4][d];
                uint32_t vs0 = Vps[kp][d], vs1 = Vps[kp + 4][d];
                mma_f16(oacc[nt], pb[0], pb[1], pb[2], pb[3], vb0, vb1);
                mma_f16(oacc[nt], pb[0], pb[1], pb[2], pb[3], vs0, vs1);
            }
        }
    }

    float inv0 = 1.0f / l0, inv1 = 1.0f / l1;
    float* yp = g_y + (size_t)(b * TT + qt * 64) * DD + h * HD;
    int r0 = rowbase + gid, r1 = r0 + 8;
#pragma unroll
    for (int nt = 0; nt < 8; nt++) {
        int c = (nt << 3) + (tig << 1);
        *(float2*)(yp + (size_t)r0 * DD + c) =
            make_float2(oacc[nt][0] * inv0, oacc[nt][1] * inv0);
        *(float2*)(yp + (size_t)r1 * DD + c) =
            make_float2(oacc[nt][2] * inv1, oacc[nt][3] * inv1);
    }
}

// ---------------------------------------------------------------------------
extern "C" void kernel_launch(void* const* d_in, const int* in_sizes, int n_in,
                              void* d_out, int out_size) {
    (void)in_sizes; (void)n_in; (void)out_size;
    const float* x      = (const float*)d_in[0];
    const float* w_q    = (const float*)d_in[1];
    const float* w_k    = (const float*)d_in[2];
    const float* w_v    = (const float*)d_in[3];
    const float* w_proj = (const float*)d_in[4];
    const float* q_gain = (const float*)d_in[5];
    float* out = (float*)d_out;

    void* p;
    cudaGetSymbolAddress(&p, g_q); float* gq = (float*)p;
    cudaGetSymbolAddress(&p, g_k); float* gk = (float*)p;
    cudaGetSymbolAddress(&p, g_v); float* gv = (float*)p;
    cudaGetSymbolAddress(&p, g_y); float* gy = (float*)p;

    qkv_gemm<<<dim3(16, 64), 256>>>(x, w_q, w_k, w_v, gq, gk, gv);

    normrope_kernel<<<(NTOK * (NH + NKV)) / 8, 256>>>(q_gain);

    attn_f16<<<dim3(TT / 64, BB * NH), 128>>>();

    sgemm_f16<<<dim3(8, 64), 256>>>(gy, w_proj, out, 512);
}